// round 3
// baseline (speedup 1.0000x reference)
#include <cuda_runtime.h>

// Problem constants
#define NB      8
#define NS      8192
#define DIM     1024
#define NE      16
#define NTOK    (NB * NS)        // 65536 tokens
#define C4      (DIM / 4)        // 256 float4 per token row
#define CHUNKS  (C4 / 32)        // 8 float4 chunks per lane

// Tiling
#define T       4                // tokens per warp (amortizes W smem reads)
#define WARPS   8
#define THREADS (WARPS * 32)
#define TOK_PER_BLOCK (WARPS * T)                 // 32
#define GRID    (NTOK / TOK_PER_BLOCK)            // 2048

#define SMEM_BYTES (NE * DIM * 4 + WARPS * (T * NE) * 4)  // 64KB W + 2KB logits

__global__ __launch_bounds__(THREADS, 2) void gating_kernel(
    const float* __restrict__ x,
    const float* __restrict__ W,
    const float* __restrict__ bias,
    float* __restrict__ out)
{
    extern __shared__ float smem[];
    float4* sW   = (float4*)smem;                  // [NE][C4] float4 = 64KB
    float*  sLog = smem + NE * DIM;                // [WARPS][64]

    // Cooperative load of W into shared (stays for whole block)
    {
        const float4* Wg = (const float4*)W;
        #pragma unroll
        for (int i = threadIdx.x; i < NE * C4; i += THREADS) sW[i] = Wg[i];
    }
    __syncthreads();

    const int warp = threadIdx.x >> 5;
    const int lane = threadIdx.x & 31;
    const int token0 = (blockIdx.x * WARPS + warp) * T;

    // 64 accumulators: v[t*NE + e]
    float v[T * NE];
    #pragma unroll
    for (int k = 0; k < T * NE; k++) v[k] = 0.0f;

    const float4* x4 = (const float4*)x + (size_t)token0 * C4;

    // Main loop: lane handles float4 columns {lane + 32*i}.
    // Per chunk: 4 LDG.128 (x, 4 tokens, independent -> MLP=4),
    //            16 LDS.128 (W), 256 FFMA.
    for (int i = 0; i < CHUNKS; i++) {
        const int c = lane + 32 * i;
        float4 xv[T];
        #pragma unroll
        for (int t = 0; t < T; t++) xv[t] = x4[(size_t)t * C4 + c];

        #pragma unroll
        for (int e = 0; e < NE; e++) {
            float4 wv = sW[e * C4 + c];
            #pragma unroll
            for (int t = 0; t < T; t++) {
                float a = v[t * NE + e];
                a = fmaf(xv[t].x, wv.x, a);
                a = fmaf(xv[t].y, wv.y, a);
                a = fmaf(xv[t].z, wv.z, a);
                a = fmaf(xv[t].w, wv.w, a);
                v[t * NE + e] = a;
            }
        }
    }

    // Value-splitting butterfly reduce: 64 values over 32 lanes.
    // Position j's original index gains offset 2m*bit(lane,m) at stage m;
    // total offset = 2*lane, so lane l ends holding fully-reduced
    // indices 2l and 2l+1 (index = t*NE + e).
    #pragma unroll
    for (int m = 16; m >= 1; m >>= 1) {
        const int half = 2 * m;
        const bool hi = (lane & m) != 0;
        #pragma unroll
        for (int j = 0; j < half; j++) {
            float send = hi ? v[j] : v[j + half];
            float keep = hi ? v[j + half] : v[j];
            v[j] = keep + __shfl_xor_sync(0xffffffffu, send, m);
        }
    }

    // Stage reduced logits through shared so lanes 0..T-1 gather their token.
    sLog[warp * (T * NE) + 2 * lane + 0] = v[0];
    sLog[warp * (T * NE) + 2 * lane + 1] = v[1];
    __syncwarp();

    if (lane < T) {
        const int token = token0 + lane;
        const float* myLog = sLog + warp * (T * NE) + lane * NE;

        float lg[NE];
        float mx = -1e30f;
        #pragma unroll
        for (int e = 0; e < NE; e++) {
            lg[e] = myLog[e] + __ldg(&bias[e]);
            mx = fmaxf(mx, lg[e]);
        }
        float s = 0.0f;
        #pragma unroll
        for (int e = 0; e < NE; e++) {
            lg[e] = __expf(lg[e] - mx);
            s += lg[e];
        }
        const float inv = 1.0f / s;

        // top-2 (strict > keeps first index on ties, matching jax top_k)
        int i1 = 0; float m1 = lg[0];
        #pragma unroll
        for (int e = 1; e < NE; e++) if (lg[e] > m1) { m1 = lg[e]; i1 = e; }
        int i2 = -1; float m2 = -1.0f;
        #pragma unroll
        for (int e = 0; e < NE; e++) if (e != i1 && lg[e] > m2) { m2 = lg[e]; i2 = e; }

        float* gated = out;                         // [NE, NB, NS]
        float* wout  = out + (size_t)NE * NTOK;     // [NE, NB, NS]
        #pragma unroll
        for (int e = 0; e < NE; e++) {
            const float w = lg[e] * inv;
            wout [(size_t)e * NTOK + token] = w;
            gated[(size_t)e * NTOK + token] = (e == i1 || e == i2) ? w : 0.0f;
        }
    }
}

extern "C" void kernel_launch(void* const* d_in, const int* in_sizes, int n_in,
                              void* d_out, int out_size)
{
    (void)in_sizes; (void)n_in; (void)out_size;
    const float* x = (const float*)d_in[0];
    const float* W = (const float*)d_in[1];
    const float* b = (const float*)d_in[2];
    float* out = (float*)d_out;

    cudaFuncSetAttribute(gating_kernel,
                         cudaFuncAttributeMaxDynamicSharedMemorySize, SMEM_BYTES);
    gating_kernel<<<GRID, THREADS, SMEM_BYTES>>>(x, W, b, out);
}

// round 4
// speedup vs baseline: 1.0280x; 1.0280x over previous
#include <cuda_runtime.h>

// Problem constants
#define NB      8
#define NS      8192
#define DIM     1024
#define NE      16
#define NTOK    (NB * NS)        // 65536 tokens
#define C4      (DIM / 4)        // 256 float4 per token row
#define CHUNKS  (C4 / 32)        // 8 float4 chunks per lane

// Tiling: warp-pair covers 8 tokens x 16 experts; each warp 8 tokens x 8 experts
#define T       8                // tokens per warp
#define EH      8                // experts per warp (half of NE)
#define WARPS   8                // 4 warp-pairs
#define THREADS (WARPS * 32)
#define TOK_PER_BLOCK 32         // 4 pairs * 8 tokens
#define GRID    (NTOK / TOK_PER_BLOCK)            // 2048

#define SMEM_BYTES (NE * DIM * 4 + WARPS * 64 * 4)  // 64KB W + 2KB logits

__global__ __launch_bounds__(THREADS, 2) void gating_kernel(
    const float* __restrict__ x,
    const float* __restrict__ W,
    const float* __restrict__ bias,
    float* __restrict__ out)
{
    extern __shared__ float smem[];
    float4* sW   = (float4*)smem;                  // [NE][C4] float4 = 64KB
    float*  sLog = smem + NE * DIM;                // [WARPS][64]

    // Cooperative load of W into shared (stays for whole block)
    {
        const float4* Wg = (const float4*)W;
        #pragma unroll
        for (int i = threadIdx.x; i < NE * C4; i += THREADS) sW[i] = Wg[i];
    }
    __syncthreads();

    const int warp = threadIdx.x >> 5;
    const int lane = threadIdx.x & 31;
    const int pair = warp >> 1;        // 0..3, which 8-token group
    const int half = warp & 1;         // 0..1, which 8-expert half
    const int token0 = blockIdx.x * TOK_PER_BLOCK + pair * T;

    // 64 accumulators: v[t*EH + e]
    float v[T * EH];
    #pragma unroll
    for (int k = 0; k < T * EH; k++) v[k] = 0.0f;

    const float4* x4  = (const float4*)x + (size_t)token0 * C4;
    const float4* sWh = sW + half * EH * C4;

    // Main loop: lane handles float4 columns {lane + 32*i}.
    // Per chunk per warp: 8 LDG.128 (x, paired warp's dupes hit L1),
    //                     8 LDS.128 (W) -> 32 FFMA each, 256 FFMA total.
    for (int i = 0; i < CHUNKS; i++) {
        const int c = lane + 32 * i;
        float4 xv[T];
        #pragma unroll
        for (int t = 0; t < T; t++) xv[t] = x4[(size_t)t * C4 + c];

        #pragma unroll
        for (int e = 0; e < EH; e++) {
            float4 wv = sWh[e * C4 + c];
            #pragma unroll
            for (int t = 0; t < T; t++) {
                float a = v[t * EH + e];
                a = fmaf(xv[t].x, wv.x, a);
                a = fmaf(xv[t].y, wv.y, a);
                a = fmaf(xv[t].z, wv.z, a);
                a = fmaf(xv[t].w, wv.w, a);
                v[t * EH + e] = a;
            }
        }
    }

    // Value-splitting butterfly reduce: 64 values over 32 lanes.
    // Position j's original index gains offset 2m*bit(lane,m) at stage m;
    // total offset = 2*lane, so lane l ends with fully-reduced
    // indices 2l and 2l+1 (index = t*EH + e).
    #pragma unroll
    for (int m = 16; m >= 1; m >>= 1) {
        const int hlf = 2 * m;
        const bool hi = (lane & m) != 0;
        #pragma unroll
        for (int j = 0; j < hlf; j++) {
            float send = hi ? v[j] : v[j + hlf];
            float keep = hi ? v[j + hlf] : v[j];
            v[j] = keep + __shfl_xor_sync(0xffffffffu, send, m);
        }
    }

    // Stage reduced logits: slot s of warp w holds token s/8 (of pair w/2),
    // expert (w&1)*8 + s%8.
    sLog[warp * 64 + 2 * lane + 0] = v[0];
    sLog[warp * 64 + 2 * lane + 1] = v[1];
    __syncthreads();

    // Epilogue: warp 0 handles all 32 tokens, token = blockbase + lane.
    // Output stores are fully coalesced 128B segments per expert.
    if (warp == 0) {
        const int p = lane >> 3;          // which pair's logits
        const int t = lane & 7;           // token within pair
        const int token = blockIdx.x * TOK_PER_BLOCK + lane;
        const float* lo = sLog + (2 * p)     * 64 + t * EH;  // experts 0..7
        const float* hi = sLog + (2 * p + 1) * 64 + t * EH;  // experts 8..15

        float lg[NE];
        float mx = -1e30f;
        #pragma unroll
        for (int e = 0; e < EH; e++) {
            lg[e]      = lo[e] + __ldg(&bias[e]);
            lg[EH + e] = hi[e] + __ldg(&bias[EH + e]);
        }
        #pragma unroll
        for (int e = 0; e < NE; e++) mx = fmaxf(mx, lg[e]);
        float s = 0.0f;
        #pragma unroll
        for (int e = 0; e < NE; e++) {
            lg[e] = __expf(lg[e] - mx);
            s += lg[e];
        }
        const float inv = 1.0f / s;

        // top-2 (strict > keeps first index on ties, matching jax top_k)
        int i1 = 0; float m1 = lg[0];
        #pragma unroll
        for (int e = 1; e < NE; e++) if (lg[e] > m1) { m1 = lg[e]; i1 = e; }
        int i2 = -1; float m2 = -1.0f;
        #pragma unroll
        for (int e = 0; e < NE; e++) if (e != i1 && lg[e] > m2) { m2 = lg[e]; i2 = e; }

        float* gated = out;                         // [NE, NB, NS]
        float* wout  = out + (size_t)NE * NTOK;     // [NE, NB, NS]
        #pragma unroll
        for (int e = 0; e < NE; e++) {
            const float w = lg[e] * inv;
            wout [(size_t)e * NTOK + token] = w;
            gated[(size_t)e * NTOK + token] = (e == i1 || e == i2) ? w : 0.0f;
        }
    }
}

extern "C" void kernel_launch(void* const* d_in, const int* in_sizes, int n_in,
                              void* d_out, int out_size)
{
    (void)in_sizes; (void)n_in; (void)out_size;
    const float* x = (const float*)d_in[0];
    const float* W = (const float*)d_in[1];
    const float* b = (const float*)d_in[2];
    float* out = (float*)d_out;

    cudaFuncSetAttribute(gating_kernel,
                         cudaFuncAttributeMaxDynamicSharedMemorySize, SMEM_BYTES);
    gating_kernel<<<GRID, THREADS, SMEM_BYTES>>>(x, W, b, out);
}